// round 1
// baseline (speedup 1.0000x reference)
#include <cuda_runtime.h>
#include <cuda_bf16.h>

// BBAStar: 8-connected grid shortest path, B=128 batches of 32x32 grids.
// dist fixed point: dist[v] = min(dist0[v], w[v] + min over 8 neighbors dist[u])
// computed via racy in-place relaxation (converges to the same float fixed
// point as the reference's 1024 Jacobi sweeps, since float add is monotone
// and path-cost accumulation order source->v is fixed).
// Then greedy backtrack from target following min-dist neighbor, with the
// reference's tie-break (first occurrence in OFFS order via strict '<').

#define BN 128
#define HN 32
#define WN 32
#define PW 34           // padded width
#define INF_F 1000000000.0f
#define EPS_F 1e-6f

__global__ void __launch_bounds__(1024, 1)
bba_kernel(const float* __restrict__ weights,
           const int*   __restrict__ source,
           const int*   __restrict__ target,
           float*       __restrict__ out)
{
    __shared__ float dist[PW * PW];   // 34x34, INF-padded border
    __shared__ float wsh[HN * WN];
    __shared__ int   changed;

    const int b   = blockIdx.x;
    const int tid = threadIdx.x;
    const int r   = tid >> 5;
    const int c   = tid & 31;

    // Zero this batch's output slice (d_out is poisoned to 0xAA).
    out[b * (HN * WN) + tid] = 0.0f;

    // Init padded dist to INF.
    for (int i = tid; i < PW * PW; i += 1024) dist[i] = INF_F;

    // Load weights (+EPS, matching reference float32 math).
    const float wv = weights[b * (HN * WN) + tid] + EPS_F;
    wsh[tid] = wv;

    const int sr = source[2 * b + 0];
    const int sc = source[2 * b + 1];
    const int tr = target[2 * b + 0];
    const int tc = target[2 * b + 1];

    __syncthreads();

    if (tid == 0) {
        dist[(sr + 1) * PW + (sc + 1)] = wsh[sr * WN + sc];
    }
    __syncthreads();

    const int idx = (r + 1) * PW + (c + 1);

    // Relax to convergence. In-place, racy reads are fine: every value in
    // dist is a valid monotone-decreasing float path cost; we terminate only
    // when a full pass makes zero changes => true fixed point (identical to
    // the reference's converged Jacobi result).
    for (;;) {
        __syncthreads();                 // all threads saw previous 'changed'
        if (tid == 0) changed = 0;
        __syncthreads();

        float nm = fminf(fminf(fminf(dist[idx - PW - 1], dist[idx - PW]),
                               fminf(dist[idx - PW + 1], dist[idx - 1])),
                         fminf(fminf(dist[idx + 1],      dist[idx + PW - 1]),
                               fminf(dist[idx + PW],     dist[idx + PW + 1])));
        float v = wv + nm;
        if (v < dist[idx]) {
            dist[idx] = v;
            changed = 1;                 // benign race, any writer sets it
        }
        __syncthreads();
        if (!changed) break;
    }

    // Greedy backtrack from target to source (thread 0).
    // Padded INF border exactly reproduces the reference's invalid->INF
    // candidate masking; strict '<' in OFFS order reproduces jnp.argmin's
    // first-occurrence tie-break.
    if (tid == 0) {
        int cr = tr, cc = tc;
        float* o = out + b * (HN * WN);
        // OFFS order: (-1,-1),(-1,0),(-1,1),(0,-1),(0,1),(1,-1),(1,0),(1,1)
        const int drs[8] = {-1, -1, -1,  0, 0,  1, 1, 1};
        const int dcs[8] = {-1,  0,  1, -1, 1, -1, 0, 1};
        for (int step = 0; step < HN * WN; ++step) {
            o[cr * WN + cc] = 1.0f;
            if (cr == sr && cc == sc) break;
            float best = INF_F;
            int br = cr, bc = cc;
            #pragma unroll
            for (int k = 0; k < 8; ++k) {
                int nr = cr + drs[k];
                int nc = cc + dcs[k];
                float dv = dist[(nr + 1) * PW + (nc + 1)];
                if (dv < best) { best = dv; br = nr; bc = nc; }
            }
            cr = br; cc = bc;
        }
    }
}

extern "C" void kernel_launch(void* const* d_in, const int* in_sizes, int n_in,
                              void* d_out, int out_size)
{
    const float* weights = (const float*)d_in[0];
    const int*   source  = (const int*)d_in[1];
    const int*   target  = (const int*)d_in[2];
    float*       out     = (float*)d_out;

    bba_kernel<<<BN, 1024>>>(weights, source, target, out);
}

// round 2
// speedup vs baseline: 1.2125x; 1.2125x over previous
#include <cuda_runtime.h>
#include <cuda_bf16.h>

// BBAStar: 8-connected grid shortest path, B=128 batches of 32x32 grids.
// Racy in-place monotone relaxation to the float fixed point (identical to the
// reference's 1024 Jacobi sweeps: float path-cost accumulation order is fixed
// source->v and min is monotone), then greedy backtrack with the reference's
// first-occurrence tie-break.
//
// R1 change: barrier-free relaxation epochs. K unsynchronized volatile passes
// per epoch, 3 barriers per epoch only for the convergence flag (was 3 barriers
// PER PASS). Own-cell dist cached in a register (write-through to smem).

#define BN 128
#define HN 32
#define WN 32
#define PW 34           // padded width
#define INF_F 1000000000.0f
#define EPS_F 1e-6f
#define KPASS 6

__global__ void __launch_bounds__(1024, 1)
bba_kernel(const float* __restrict__ weights,
           const int*   __restrict__ source,
           const int*   __restrict__ target,
           float*       __restrict__ out)
{
    __shared__ float dist[PW * PW];   // 34x34, INF-padded border
    __shared__ int   changed;

    volatile float* vdist = dist;

    const int b   = blockIdx.x;
    const int tid = threadIdx.x;
    const int r   = tid >> 5;
    const int c   = tid & 31;

    // Zero this batch's output slice (d_out is poisoned to 0xAA).
    out[b * (HN * WN) + tid] = 0.0f;

    // Init padded dist to INF.
    for (int i = tid; i < PW * PW; i += 1024) dist[i] = INF_F;
    if (tid == 0) changed = 0;

    // Weights (+EPS, matching reference float32 math).
    const float wv = weights[b * (HN * WN) + tid] + EPS_F;

    const int sr = source[2 * b + 0];
    const int sc = source[2 * b + 1];
    const int tr = target[2 * b + 0];
    const int tc = target[2 * b + 1];

    const int idx = (r + 1) * PW + (c + 1);
    const bool is_src = (r == sr) && (c == sc);

    __syncthreads();

    float myd = INF_F;
    if (is_src) {
        myd = wv;                 // dist0 at source = w[source]
        dist[idx] = myd;
    }
    __syncthreads();

    // Epoch-based relaxation: KPASS racy passes, then agree on convergence.
    // Monotone-decreasing values => any interleaving converges to the unique
    // float fixed point; an epoch with zero changes after a barrier proves it.
    for (;;) {
        #pragma unroll 1
        for (int k = 0; k < KPASS; ++k) {
            float nm = fminf(fminf(fminf(vdist[idx - PW - 1], vdist[idx - PW]),
                                   fminf(vdist[idx - PW + 1], vdist[idx - 1])),
                             fminf(fminf(vdist[idx + 1],      vdist[idx + PW - 1]),
                                   fminf(vdist[idx + PW],     vdist[idx + PW + 1])));
            float v = wv + nm;
            if (v < myd) {
                myd = v;
                vdist[idx] = v;
                changed = 1;          // benign race
            }
        }
        __syncthreads();              // all epoch writes visible
        int c0 = changed;             // everyone reads the same value
        __syncthreads();              // all reads done before any reset
        if (!c0) break;
        if (tid == 0) changed = 0;
        __syncthreads();              // reset visible before next epoch writes
    }

    // Greedy backtrack from target to source (thread 0).
    // INF border reproduces invalid->INF masking; strict '<' in OFFS order
    // reproduces jnp.argmin's first-occurrence tie-break.
    if (tid == 0) {
        int cr = tr, cc = tc;
        float* o = out + b * (HN * WN);
        const int drs[8] = {-1, -1, -1,  0, 0,  1, 1, 1};
        const int dcs[8] = {-1,  0,  1, -1, 1, -1, 0, 1};
        for (int step = 0; step < HN * WN; ++step) {
            o[cr * WN + cc] = 1.0f;
            if (cr == sr && cc == sc) break;
            float best = INF_F;
            int br = cr, bc = cc;
            #pragma unroll
            for (int k = 0; k < 8; ++k) {
                int nr = cr + drs[k];
                int nc = cc + dcs[k];
                float dv = dist[(nr + 1) * PW + (nc + 1)];
                if (dv < best) { best = dv; br = nr; bc = nc; }
            }
            cr = br; cc = bc;
        }
    }
}

extern "C" void kernel_launch(void* const* d_in, const int* in_sizes, int n_in,
                              void* d_out, int out_size)
{
    const float* weights = (const float*)d_in[0];
    const int*   source  = (const int*)d_in[1];
    const int*   target  = (const int*)d_in[2];
    float*       out     = (float*)d_out;

    bba_kernel<<<BN, 1024>>>(weights, source, target, out);
}